// round 16
// baseline (speedup 1.0000x reference)
#include <cuda_runtime.h>
#include <cuda_bf16.h>
#include <math.h>
#include <stdint.h>

// Problem constants
#define NN   4096
#define IND  512
#define OUTD 256
#define KH   3
#define ALPHA 0.2f
#define BETA  0.1f
#define ETA   0.5f

// GEMM tiling
#define TM 128
#define TN 64
#define KC 64
#define KCA 128
#define NITER_ATT (NN / KCA)    // 32
#define NITER_WH  (IND / KC)    // 8

#if defined(__CUDA_ARCH__)
#  if (__CUDA_ARCH__ >= 1000) && (defined(__CUDA_ARCH_FEAT_SM103_ALL) || defined(__CUDA_ARCH_SPECIFIC__) || defined(__CUDA_ARCH_FAMILY_SPECIFIC__))
#    define USE_TC 1
#  else
#    define USE_TC 0
#  endif
#else
#  define USE_TC 0
#endif

// ---------------- device scratch ----------------
__device__ __nv_bfloat16 g_att_hi[(size_t)NN * NN];
__device__ float g_Wh0[(size_t)NN * OUTD];
__device__ __nv_bfloat16 g_BT_hi[(size_t)OUTD * NN];
__device__ __nv_bfloat16 g_BT_lo[(size_t)OUTD * NN];
__device__ __nv_bfloat16 g_h_hi[(size_t)NN * IND];
__device__ __nv_bfloat16 g_h_lo[(size_t)NN * IND];
__device__ __nv_bfloat16 g_WT_hi[(size_t)OUTD * IND];
__device__ __nv_bfloat16 g_WT_lo[(size_t)OUTD * IND];
__device__ float g_u[NN], g_v[NN];
__device__ float g_E1[NN], g_F1[NN];
__device__ float g_E2[NN], g_F2[NN];
__device__ float g_wd0[IND], g_wd1[IND];
__device__ unsigned g_ord[4];

// ---------------- ordered-float encoding ----------------
__device__ __forceinline__ unsigned ordenc(float f) {
    unsigned b = __float_as_uint(f);
    return (b & 0x80000000u) ? ~b : (b | 0x80000000u);
}
__device__ __forceinline__ float orddec(unsigned k) {
    unsigned b = (k & 0x80000000u) ? (k & 0x7FFFFFFFu) : ~k;
    return __uint_as_float(b);
}

// ---------------- PTX helpers ----------------
__device__ __forceinline__ uint32_t smem_u32(const void* p) {
    uint32_t a;
    asm("{ .reg .u64 t; cvta.to.shared.u64 t, %1; cvt.u32.u64 %0, t; }" : "=r"(a) : "l"(p));
    return a;
}
__device__ __forceinline__ uint32_t elect_one() {
    uint32_t p;
    asm volatile("{ .reg .pred p; elect.sync _|p, 0xFFFFFFFF; selp.b32 %0, 1, 0, p; }" : "=r"(p));
    return p;
}
#define MBARRIER_INIT(addr, cnt) \
    asm volatile("mbarrier.init.shared.b64 [%0], %1;" :: "r"(addr), "r"(cnt) : "memory")
#define MBARRIER_INVAL(addr) \
    asm volatile("mbarrier.inval.shared.b64 [%0];" :: "r"(addr) : "memory")
#define MBAR_WAIT(addr, ph) do { \
    uint32_t _m = (addr); uint32_t _p = (ph); uint32_t _d; \
    asm volatile("{ .reg .pred p; mbarrier.try_wait.parity.acquire.cta.shared::cta.b64 p, [%1], %2; selp.b32 %0, 1, 0, p; }" \
        : "=r"(_d) : "r"(_m), "r"(_p) : "memory"); \
    if (!_d) { \
        asm volatile("{ .reg .pred P1; WL_%=: mbarrier.try_wait.parity.acquire.cta.shared::cta.b64 P1, [%0], %1, 0x989680; @P1 bra.uni WD_%=; bra.uni WL_%=; WD_%=: }" \
            :: "r"(_m), "r"(_p) : "memory"); \
    } } while (0)

#if USE_TC
#define TCGEN05_ALLOC(saddr, ncols) \
    asm volatile("tcgen05.alloc.cta_group::1.sync.aligned.shared::cta.b32 [%0], %1;" :: "r"(saddr), "r"(ncols) : "memory")
#define TCGEN05_DEALLOC(tmem, ncols) \
    asm volatile("tcgen05.dealloc.cta_group::1.sync.aligned.b32 %0, %1;" :: "r"(tmem), "r"(ncols))
#define TCGEN05_COMMIT(mbar) \
    asm volatile("tcgen05.commit.cta_group::1.mbarrier::arrive::one.shared::cluster.b64 [%0];" :: "r"(mbar) : "memory")
#define TCGEN05_WAIT_LD() asm volatile("tcgen05.wait::ld.sync.aligned;" ::: "memory")
#define TCGEN05_FENCE_AFTER() asm volatile("tcgen05.fence::after_thread_sync;" ::: "memory")
#define TCGEN05_FENCE_BEFORE() asm volatile("tcgen05.fence::before_thread_sync;" ::: "memory")
#define TCGEN05_LD_X32(r, addr) \
    asm volatile("tcgen05.ld.sync.aligned.32x32b.x32.b32 " \
        "{%0,%1,%2,%3,%4,%5,%6,%7,%8,%9,%10,%11,%12,%13,%14,%15," \
        "%16,%17,%18,%19,%20,%21,%22,%23,%24,%25,%26,%27,%28,%29,%30,%31}, [%32];" \
        : "=r"((r)[0]),"=r"((r)[1]),"=r"((r)[2]),"=r"((r)[3]),"=r"((r)[4]),"=r"((r)[5]),"=r"((r)[6]),"=r"((r)[7]), \
          "=r"((r)[8]),"=r"((r)[9]),"=r"((r)[10]),"=r"((r)[11]),"=r"((r)[12]),"=r"((r)[13]),"=r"((r)[14]),"=r"((r)[15]), \
          "=r"((r)[16]),"=r"((r)[17]),"=r"((r)[18]),"=r"((r)[19]),"=r"((r)[20]),"=r"((r)[21]),"=r"((r)[22]),"=r"((r)[23]), \
          "=r"((r)[24]),"=r"((r)[25]),"=r"((r)[26]),"=r"((r)[27]),"=r"((r)[28]),"=r"((r)[29]),"=r"((r)[30]),"=r"((r)[31]) \
        : "r"(addr))

static __device__ __forceinline__ uint64_t make_desc(uint32_t addr) {
    const uint64_t base = (uint64_t(2) << 61) | (uint64_t(1) << 46) |
                          (uint64_t(64) << 32) | (uint64_t(1) << 16);
    return base | ((uint64_t)(addr >> 4) & 0x3FFF);
}

#define IDESC ((1u << 4) | (1u << 7) | (1u << 10) | ((TN / 8) << 17) | ((TM / 16) << 24))

__device__ __forceinline__ void mma_ss_f16(uint32_t d, uint64_t a, uint64_t b,
                                           uint32_t idesc, uint32_t acc) {
    asm volatile(
        "{\n\t.reg .pred p;\n\t"
        "setp.ne.u32 p, %4, 0;\n\t"
        "tcgen05.mma.cta_group::1.kind::f16 [%0], %1, %2, %3, {%5,%5,%5,%5}, p;\n\t}"
        :: "r"(d), "l"(a), "l"(b), "r"(idesc), "r"(acc), "r"(0u) : "memory");
}
#endif  // USE_TC

__device__ __forceinline__ void cpa16(uint32_t s, const void* g) {
    asm volatile("cp.async.cg.shared.global [%0], [%1], 16;" :: "r"(s), "l"(g));
}

// ---------------- K0: fused prep ----------------
#define PREP_HSPLIT 2048
#define PREP_WD     512
#define PREP_WT     128
__global__ void __launch_bounds__(256)
prep_all(const float* __restrict__ h, const float* __restrict__ W,
         const float* __restrict__ disc) {
    __shared__ float shbuf[32 * 33];
    int b = blockIdx.x;
    int t = threadIdx.x;

    if (b < PREP_HSPLIT) {
        int idx = b * 256 + t;
        const float4* h4 = (const float4*)h;
        float4 v = h4[idx];
        __nv_bfloat16 hx = __float2bfloat16(v.x), hy = __float2bfloat16(v.y);
        __nv_bfloat16 hz = __float2bfloat16(v.z), hw = __float2bfloat16(v.w);
        __nv_bfloat162* hi2 = (__nv_bfloat162*)g_h_hi;
        __nv_bfloat162* lo2 = (__nv_bfloat162*)g_h_lo;
        hi2[2 * idx]     = __nv_bfloat162(hx, hy);
        hi2[2 * idx + 1] = __nv_bfloat162(hz, hw);
        lo2[2 * idx]     = __nv_bfloat162(__float2bfloat16(v.x - __bfloat162float(hx)),
                                          __float2bfloat16(v.y - __bfloat162float(hy)));
        lo2[2 * idx + 1] = __nv_bfloat162(__float2bfloat16(v.z - __bfloat162float(hz)),
                                          __float2bfloat16(v.w - __bfloat162float(hw)));
    } else if (b < PREP_HSPLIT + PREP_WD) {
        int i = b - PREP_HSPLIT;
        float d0 = disc[t];
        float d1 = disc[OUTD + t];
        float p0 = 0.f, p1 = 0.f, w = 1.f;
#pragma unroll
        for (int k = 0; k < KH; k++) {
            float wv = W[((size_t)(k * IND + i)) * OUTD + t];
            p0 += w * wv * d0;
            p1 += w * wv * d1;
            w *= ETA;
        }
        float* sh0 = shbuf;
        float* sh1 = shbuf + 256;
        sh0[t] = p0; sh1[t] = p1;
        __syncthreads();
        for (int o = 128; o; o >>= 1) {
            if (t < o) { sh0[t] += sh0[t + o]; sh1[t] += sh1[t + o]; }
            __syncthreads();
        }
        if (t == 0) { g_wd0[i] = sh0[0]; g_wd1[i] = sh1[0]; }
    } else if (b < PREP_HSPLIT + PREP_WD + PREP_WT) {
        int tb = b - (PREP_HSPLIT + PREP_WD);
        int r0 = (tb & 15) * 32;
        int c0 = (tb >> 4) * 32;
        float (*sh)[33] = (float(*)[33])shbuf;
        int tx = t & 31, ty = t >> 5;
#pragma unroll
        for (int it = 0; it < 4; it++) {
            int r = ty + 8 * it;
            sh[r][tx] = W[(size_t)(r0 + r) * OUTD + c0 + tx];
        }
        __syncthreads();
#pragma unroll
        for (int it = 0; it < 4; it++) {
            int n = c0 + ty + 8 * it;
            int k = r0 + tx;
            float v = sh[tx][ty + 8 * it];
            __nv_bfloat16 hi = __float2bfloat16(v);
            g_WT_hi[(size_t)n * IND + k] = hi;
            g_WT_lo[(size_t)n * IND + k] = __float2bfloat16(v - __bfloat162float(hi));
        }
    } else {
        if (t == 0) {
            g_ord[0] = 0xFFFFFFFFu;
            g_ord[1] = 0u;
            g_ord[2] = 0xFFFFFFFFu;
            g_ord[3] = 0u;
        }
    }
}

// ---------------- K2: u/v + atomic min/max ----------------
__global__ void __launch_bounds__(256) k_uv(const float* __restrict__ h) {
    __shared__ float su[8], sv[8];
    int gw = (blockIdx.x * blockDim.x + threadIdx.x) >> 5;
    int lane = threadIdx.x & 31;
    int wid = threadIdx.x >> 5;
    const float* hr = h + (size_t)gw * IND;
    float u = 0.f, v = 0.f;
#pragma unroll 4
    for (int i = lane; i < IND; i += 32) {
        float hv = hr[i];
        u += hv * g_wd0[i];
        v += hv * g_wd1[i];
    }
#pragma unroll
    for (int o = 16; o; o >>= 1) {
        u += __shfl_down_sync(0xffffffffu, u, o);
        v += __shfl_down_sync(0xffffffffu, v, o);
    }
    if (lane == 0) {
        g_u[gw] = u; g_v[gw] = v;
        su[wid] = u; sv[wid] = v;
    }
    __syncthreads();
    if (threadIdx.x == 0) {
        float umin = su[0], umax = su[0], vmin = sv[0], vmax = sv[0];
#pragma unroll
        for (int i = 1; i < 8; i++) {
            umin = fminf(umin, su[i]); umax = fmaxf(umax, su[i]);
            vmin = fminf(vmin, sv[i]); vmax = fmaxf(vmax, sv[i]);
        }
        atomicMin(&g_ord[0], ordenc(umin));
        atomicMax(&g_ord[1], ordenc(umax));
        atomicMin(&g_ord[2], ordenc(vmin));
        atomicMax(&g_ord[3], ordenc(vmax));
    }
}

// ---------------- K5+K6 fused: s1/s2 (-> E/F tables) + Wh0^T hi/lo ----------
__global__ void __launch_bounds__(256)
k_sbt(const float* __restrict__ a) {
    __shared__ float sh[32][257];
    __shared__ float s_a1[OUTD], s_a2[OUTD];
    int tx = threadIdx.x & 31;
    int ty = threadIdx.x >> 5;
    int tid = threadIdx.x;
    int m0 = blockIdx.x * 32;

    s_a1[tid] = a[tid];
    s_a2[tid] = a[OUTD + tid];
#pragma unroll
    for (int i = 0; i < 4; i++) {
        int m = ty + 8 * i;
#pragma unroll
        for (int j = 0; j < 8; j++) {
            int n = tx + 32 * j;
            sh[m][n] = g_Wh0[(size_t)(m0 + m) * OUTD + n];
        }
    }
    __syncthreads();

#pragma unroll
    for (int i = 0; i < 4; i++) {
        int m = ty + 8 * i;
        float x1 = 0.f, x2 = 0.f;
#pragma unroll
        for (int j = 0; j < 8; j++) {
            int n = tx + 32 * j;
            float w = sh[m][n];
            x1 += w * s_a1[n];
            x2 += w * s_a2[n];
        }
#pragma unroll
        for (int o = 16; o; o >>= 1) {
            x1 += __shfl_down_sync(0xffffffffu, x1, o);
            x2 += __shfl_down_sync(0xffffffffu, x2, o);
        }
        if (tx == 0) {
            int m_g = m0 + m;
            g_E1[m_g] = __expf(x1);
            g_F1[m_g] = __expf(ALPHA * x1);
            g_E2[m_g] = __expf(x2);
            g_F2[m_g] = __expf(ALPHA * x2);
        }
    }

#pragma unroll
    for (int j = 0; j < 32; j++) {
        int n = ty + 8 * j;
        float v = sh[tx][n];
        __nv_bfloat16 hi = __float2bfloat16(v);
        g_BT_hi[(size_t)n * NN + m0 + tx] = hi;
        g_BT_lo[(size_t)n * NN + m0 + tx] = __float2bfloat16(v - __bfloat162float(hi));
    }
}

// ---------------- K7: FUSED att + dn + km (single mask pass, M-split) -------
__global__ void __launch_bounds__(256)
k_fused(const int* __restrict__ kmask, const float* __restrict__ lamda,
        float* __restrict__ dn, float* __restrict__ km, int i0) {
    __shared__ float e2s[NN];
    __shared__ float f2s[NN];
    __shared__ float vs[NN];
    __shared__ float red[256];
    __shared__ float s_inv;
    int i = blockIdx.x + i0;
    int t = threadIdx.x;  // 256
    for (int q = t; q < NN; q += 256) {
        e2s[q] = g_E2[q];
        f2s[q] = g_F2[q];
        vs[q]  = g_v[q];
    }
    if (t == 0) {
        float umin = orddec(g_ord[0]), umax = orddec(g_ord[1]);
        float vmin = orddec(g_ord[2]), vmax = orddec(g_ord[3]);
        s_inv = 1.f / fmaxf(fabsf(umin + vmin), umax + vmax);
    }
    __syncthreads();

    float E1 = g_E1[i];
    float F1 = g_F1[i];
    float ui = g_u[i];
    float lam = lamda[0];
    float inv = s_inv;
    size_t rb = (size_t)i * NN;
    size_t plane = (size_t)NN * NN;
    const int4* m0p = (const int4*)(kmask + rb);
    const int4* m1p = (const int4*)(kmask + plane + rb);
    const int4* m2p = (const int4*)(kmask + 2 * plane + rb);

    float p[16];
    uint32_t b0 = 0, b1 = 0, b2 = 0;
    float sum = 0.f;
#pragma unroll
    for (int q = 0; q < 4; q++) {
        int j4 = t + 256 * q;
        int4 ma = __ldcs(&m0p[j4]);
        int4 mb = __ldcs(&m1p[j4]);
        int4 mc = __ldcs(&m2p[j4]);
        int base = 4 * j4;
#pragma unroll
        for (int c = 0; c < 4; c++) {
            int e = 4 * q + c;
            int a0 = (c == 0) ? ma.x : (c == 1) ? ma.y : (c == 2) ? ma.z : ma.w;
            int a1 = (c == 0) ? mb.x : (c == 1) ? mb.y : (c == 2) ? mb.z : mb.w;
            int a2 = (c == 0) ? mc.x : (c == 1) ? mc.y : (c == 2) ? mc.z : mc.w;
            b0 |= (uint32_t)a0 << e;
            b1 |= (uint32_t)a1 << e;
            b2 |= (uint32_t)a2 << e;
            float pv = E1 * e2s[base + c];
            if (pv <= 1.f) pv = F1 * f2s[base + c];
            pv = a0 ? pv : 0.f;
            p[e] = pv;
            sum += pv;
        }
    }
    red[t] = sum; __syncthreads();
    for (int o = 128; o; o >>= 1) { if (t < o) red[t] += red[t + o]; __syncthreads(); }
    float ri = 1.f / red[0];

    uint2* ah = (uint2*)(g_att_hi + rb);
    float4* dn4 = (float4*)(dn + rb);
    float4* k04 = (float4*)(km + rb);
    float4* k14 = (float4*)(km + plane + rb);
    float4* k24 = (float4*)(km + 2 * plane + rb);

#pragma unroll
    for (int q = 0; q < 4; q++) {
        int j4 = t + 256 * q;
        __nv_bfloat162 lo2(__float2bfloat16(p[4 * q + 0] * ri),
                           __float2bfloat16(p[4 * q + 1] * ri));
        __nv_bfloat162 hi2(__float2bfloat16(p[4 * q + 2] * ri),
                           __float2bfloat16(p[4 * q + 3] * ri));
        uint2 att_out;
        att_out.x = *(uint32_t*)&lo2;
        att_out.y = *(uint32_t*)&hi2;
        ah[j4] = att_out;

        float4 dno, k0, k1, k2;
#pragma unroll
        for (int c = 0; c < 4; c++) {
            int e = 4 * q + c;
            int a0 = (b0 >> e) & 1;
            int a1 = (b1 >> e) & 1;
            int a2 = (b2 >> e) & 1;
            float d = (ui + vs[4 * j4 + c]) * inv;
            int pos = d > lam;
            int neg = d < -lam;
            float dv = (pos | neg) ? 0.f : d;
            int km0 = a0 - a0 * pos - a1 * neg;
            int km1 = a1 + a0 * pos - a1 * pos + a1 * neg - a2 * neg;
            int km2 = a2 + a1 * pos + a2 * neg;
            float f0 = (float)km0, f1 = (float)km1, f2 = (float)km2;
            if (c == 0) { dno.x = dv; k0.x = f0; k1.x = f1; k2.x = f2; }
            else if (c == 1) { dno.y = dv; k0.y = f0; k1.y = f1; k2.y = f2; }
            else if (c == 2) { dno.z = dv; k0.z = f0; k1.z = f1; k2.z = f2; }
            else { dno.w = dv; k0.w = f0; k1.w = f1; k2.w = f2; }
        }
        __stcs(&dn4[j4], dno);
        __stcs(&k04[j4], k0);
        __stcs(&k14[j4], k1);
        __stcs(&k24[j4], k2);
    }
}

// ---------------- K8a: tcgen05 GEMM (TM128/TN64, KC=128, 2-stage, M-split) ---
__global__ void __launch_bounds__(256)
gemm_att(float* __restrict__ outp, int mb0) {
#if USE_TC
    extern __shared__ char smem[];
    const uint32_t sb = smem_u32(smem);
    int tid = threadIdx.x, wid = tid >> 5, lane = tid & 31;
    int m0 = (blockIdx.y + mb0) * TM;
    int n0 = blockIdx.x * TN;

    if (wid == 0) TCGEN05_ALLOC(sb + 0, 256);
    if (tid == 0) {
        MBARRIER_INIT(sb + 8, 1);
        MBARRIER_INIT(sb + 16, 1);
        MBARRIER_INIT(sb + 24, 1);
    }
    __syncthreads();
    uint32_t tmem;
    asm volatile("ld.shared.b32 %0, [%1];" : "=r"(tmem) : "r"(sb + 0));

    const char* gAh = (const char*)g_att_hi + (size_t)m0 * (NN * 2);
    const char* gBh = (const char*)g_BT_hi + (size_t)n0 * (NN * 2);
    const char* gBl = (const char*)g_BT_lo + (size_t)n0 * (NN * 2);

#define LOAD_STAGE_A(s, kc) do { \
    uint32_t sbase = sb + 1024 + (s) * 65536; \
    _Pragma("unroll") \
    for (int i_ = 0; i_ < 8; i_++) { \
        int q_ = tid + 256 * i_; \
        int sub_ = q_ >> 10, r_ = (q_ >> 3) & 127, c_ = q_ & 7; \
        uint32_t so_ = sub_ * 16384 + r_ * 128 + (((uint32_t)(c_ ^ (r_ & 7))) << 4); \
        size_t go_ = (size_t)r_ * (NN * 2) + (size_t)(kc) * (KCA * 2) + (sub_ * 8 + c_) * 16; \
        cpa16(sbase + so_, gAh + go_); \
    } \
    _Pragma("unroll") \
    for (int i_ = 0; i_ < 4; i_++) { \
        int q_ = tid + 256 * i_; \
        int sub_ = q_ >> 9, r_ = (q_ >> 3) & 63, c_ = q_ & 7; \
        uint32_t so_ = sub_ * 8192 + r_ * 128 + (((uint32_t)(c_ ^ (r_ & 7))) << 4); \
        size_t go_ = (size_t)r_ * (NN * 2) + (size_t)(kc) * (KCA * 2) + (sub_ * 8 + c_) * 16; \
        cpa16(sbase + 32768 + so_, gBh + go_); \
        cpa16(sbase + 49152 + so_, gBl + go_); \
    } \
    asm volatile("cp.async.commit_group;"); \
} while (0)

    int ph0 = 0, ph1 = 0;
    LOAD_STAGE_A(0, 0);

    for (int kc = 0; kc < NITER_ATT; kc++) {
        int s = kc & 1;
        if (kc + 1 < NITER_ATT) {
            int sn = s ^ 1;
            if (kc >= 1) {
                if (sn == 0) { MBAR_WAIT(sb + 8, ph0); ph0 ^= 1; }
                else         { MBAR_WAIT(sb + 16, ph1); ph1 ^= 1; }
            }
            LOAD_STAGE_A(sn, kc + 1);
            asm volatile("cp.async.wait_group 1;");
        } else {
            asm volatile("cp.async.wait_group 0;");
        }
        __syncthreads();
        if (wid == 0) {
            if (elect_one()) {
                asm volatile("fence.proxy.async.shared::cta;" ::: "memory");
                uint32_t sbase = sb + 1024 + s * 65536;
#pragma unroll
                for (int sub = 0; sub < 2; sub++) {
                    uint64_t da  = make_desc(sbase + sub * 16384);
                    uint64_t dbh = make_desc(sbase + 32768 + sub * 8192);
                    uint64_t dbl = make_desc(sbase + 49152 + sub * 8192);
#pragma unroll
                    for (int ks = 0; ks < 4; ks++) {
                        uint32_t acc = (kc > 0) || (sub > 0) || (ks > 0);
                        mma_ss_f16(tmem, da + ks * 2, dbh + ks * 2, IDESC, acc);
                        mma_ss_f16(tmem, da + ks * 2, dbl + ks * 2, IDESC, 1);
                    }
                }
                TCGEN05_COMMIT(sb + 8 + s * 8);
            }
        }
    }

    if (wid == 0) {
        if (elect_one()) TCGEN05_COMMIT(sb + 24);
    }
    MBAR_WAIT(sb + 24, 0);
    TCGEN05_FENCE_AFTER();

    if (wid < 4) {
        int m = m0 + wid * 32 + lane;
        const float* whrow = g_Wh0 + (size_t)m * OUTD + n0;
        float* orow = outp + (size_t)m * OUTD + n0;
#pragma unroll
        for (int nb = 0; nb < TN; nb += 32) {
            uint32_t r[32];
            TCGEN05_LD_X32(r, tmem + nb);
            TCGEN05_WAIT_LD();
#pragma unroll
            for (int c = 0; c < 32; c++) {
                float w = 0.9f * __uint_as_float(r[c]) + 0.1f * whrow[nb + c];
                orow[nb + c] = w > 0.f ? w : expm1f(w);
            }
        }
        TCGEN05_FENCE_BEFORE();
    }
    __syncthreads();
    if (tid == 0) { MBARRIER_INVAL(sb + 8); MBARRIER_INVAL(sb + 16); MBARRIER_INVAL(sb + 24); }
    __syncthreads();
    if (wid == 0) TCGEN05_DEALLOC(tmem, 256);
#undef LOAD_STAGE_A
#else
    int tid = threadIdx.x;
    int m0 = (blockIdx.y + mb0) * TM;
    int n0 = blockIdx.x * TN;
    int tr = (tid >> 3) * 4;
    int tc = (tid & 7) * 8;
    for (int r = 0; r < 4; r++) {
        int m = m0 + tr + r;
        for (int c = 0; c < 8; c++) {
            int n = n0 + tc + c;
            float acc = 0.f;
            for (int k = 0; k < NN; k++) {
                float av = __bfloat162float(g_att_hi[(size_t)m * NN + k]);
                float bv = __bfloat162float(g_BT_hi[(size_t)n * NN + k]) +
                           __bfloat162float(g_BT_lo[(size_t)n * NN + k]);
                acc += av * bv;
            }
            float w = 0.9f * acc + 0.1f * g_Wh0[(size_t)m * OUTD + n];
            outp[(size_t)m * OUTD + n] = w > 0.f ? w : expm1f(w);
        }
    }
#endif
}

// ---------------- K8b: tcgen05 GEMM (TM128/TN64, 3-stage): g_Wh0 = h @ W0 ----
__global__ void __launch_bounds__(256)
gemm_wh() {
#if USE_TC
    extern __shared__ char smem[];
    const uint32_t sb = smem_u32(smem);
    int tid = threadIdx.x, wid = tid >> 5, lane = tid & 31;
    int m0 = blockIdx.y * TM;
    int n0 = blockIdx.x * TN;

    if (wid == 0) TCGEN05_ALLOC(sb + 0, 256);
    if (tid == 0) {
        MBARRIER_INIT(sb + 8, 1);
        MBARRIER_INIT(sb + 16, 1);
        MBARRIER_INIT(sb + 24, 1);
        MBARRIER_INIT(sb + 32, 1);
    }
    __syncthreads();
    uint32_t tmem;
    asm volatile("ld.shared.b32 %0, [%1];" : "=r"(tmem) : "r"(sb + 0));

    const char* gAh = (const char*)g_h_hi  + (size_t)m0 * (IND * 2);
    const char* gAl = (const char*)g_h_lo  + (size_t)m0 * (IND * 2);
    const char* gBh = (const char*)g_WT_hi + (size_t)n0 * (IND * 2);
    const char* gBl = (const char*)g_WT_lo + (size_t)n0 * (IND * 2);

#define LOAD_STAGE_W(s, kc) do { \
    uint32_t sbase = sb + 1024 + (s) * 49152; \
    _Pragma("unroll") \
    for (int i_ = 0; i_ < 4; i_++) { \
        int q_ = tid + 256 * i_; \
        int r_ = q_ >> 3, c_ = q_ & 7; \
        uint32_t so_ = r_ * 128 + (((uint32_t)(c_ ^ (r_ & 7))) << 4); \
        size_t go_ = (size_t)r_ * (IND * 2) + (size_t)(kc) * (KC * 2) + c_ * 16; \
        cpa16(sbase + so_,         gAh + go_); \
        cpa16(sbase + 16384 + so_, gAl + go_); \
    } \
    _Pragma("unroll") \
    for (int i_ = 0; i_ < 2; i_++) { \
        int q_ = tid + 256 * i_; \
        int r_ = q_ >> 3, c_ = q_ & 7; \
        uint32_t so_ = r_ * 128 + (((uint32_t)(c_ ^ (r_ & 7))) << 4); \
        size_t go_ = (size_t)r_ * (IND * 2) + (size_t)(kc) * (KC * 2) + c_ * 16; \
        cpa16(sbase + 32768 + so_, gBh + go_); \
        cpa16(sbase + 40960 + so_, gBl + go_); \
    } \
    asm volatile("cp.async.commit_group;"); \
} while (0)

    int ph[3] = {0, 0, 0};
    LOAD_STAGE_W(0, 0);
    LOAD_STAGE_W(1, 1);

    for (int kc = 0; kc < NITER_WH; kc++) {
        int s = kc % 3;
        if (kc + 2 < NITER_WH) {
            if (kc >= 1) {
                int rs = (kc - 1) % 3;
                MBAR_WAIT(sb + 8 + rs * 8, ph[rs]);
                ph[rs] ^= 1;
            }
            LOAD_STAGE_W((kc + 2) % 3, kc + 2);
            asm volatile("cp.async.wait_group 2;");
        } else if (kc + 1 < NITER_WH) {
            asm volatile("cp.async.wait_group 1;");
        } else {
            asm volatile("cp.async.wait_group 0;");
        }
        __syncthreads();
        if (wid == 0) {
            if (elect_one()) {
                asm volatile("fence.proxy.async.shared::cta;" ::: "memory");
                uint32_t sbase = sb + 1024 + s * 49152;
                uint64_t dah = make_desc(sbase);
                uint64_t dal = make_desc(sbase + 16384);
                uint64_t dbh = make_desc(sbase + 32768);
                uint64_t dbl = make_desc(sbase + 40960);
#pragma unroll
                for (int ks = 0; ks < 4; ks++) {
                    uint32_t acc = (kc > 0) || (ks > 0);
                    mma_ss_f16(tmem, dah + ks * 2, dbh + ks * 2, IDESC, acc);
                    mma_ss_f16(tmem, dal + ks * 2, dbh + ks * 2, IDESC, 1);
                    mma_ss_f16(tmem, dah + ks * 2, dbl + ks * 2, IDESC, 1);
                }
                TCGEN05_COMMIT(sb + 8 + s * 8);
            }
        }
    }

    if (wid == 0) {
        if (elect_one()) TCGEN05_COMMIT(sb + 32);
    }
    MBAR_WAIT(sb + 32, 0);
    TCGEN05_FENCE_AFTER();

    if (wid < 4) {
        int m = m0 + wid * 32 + lane;
        float* crow = g_Wh0 + (size_t)m * OUTD + n0;
#pragma unroll
        for (int nb = 0; nb < TN; nb += 32) {
            uint32_t r[32];
            TCGEN05_LD_X32(r, tmem + nb);
            TCGEN05_WAIT_LD();
#pragma unroll
            for (int c = 0; c < 32; c++) {
                crow[nb + c] = __uint_as_float(r[c]);
            }
        }
        TCGEN05_FENCE_BEFORE();
    }
    __syncthreads();
    if (tid == 0) {
        MBARRIER_INVAL(sb + 8); MBARRIER_INVAL(sb + 16);
        MBARRIER_INVAL(sb + 24); MBARRIER_INVAL(sb + 32);
    }
    __syncthreads();
    if (wid == 0) TCGEN05_DEALLOC(tmem, 256);
#undef LOAD_STAGE_W
#else
    int tid = threadIdx.x;
    int m0 = blockIdx.y * TM;
    int n0 = blockIdx.x * TN;
    int tr = (tid >> 3) * 4;
    int tc = (tid & 7) * 8;
    for (int r = 0; r < 4; r++) {
        int m = m0 + tr + r;
        for (int c = 0; c < 8; c++) {
            int n = n0 + tc + c;
            float acc = 0.f;
            for (int k = 0; k < IND; k++) {
                float av = __bfloat162float(g_h_hi[(size_t)m * IND + k]) +
                           __bfloat162float(g_h_lo[(size_t)m * IND + k]);
                float bv = __bfloat162float(g_WT_hi[(size_t)n * IND + k]) +
                           __bfloat162float(g_WT_lo[(size_t)n * IND + k]);
                acc += av * bv;
            }
            g_Wh0[(size_t)m * OUTD + n] = acc;
        }
    }
#endif
}

// ---------------- stream/event globals ----------------
static cudaStream_t hs_s1 = nullptr, hs_s2 = nullptr, hs_s3 = nullptr;
static cudaEvent_t hs_ev0 = nullptr, hs_ev2 = nullptr, hs_ev3 = nullptr,
                   hs_ev5 = nullptr, hs_evEnd = nullptr;
namespace {
struct HsInitStreams {
    HsInitStreams() {
        cudaStreamCreateWithFlags(&hs_s1, cudaStreamNonBlocking);
        cudaStreamCreateWithFlags(&hs_s2, cudaStreamNonBlocking);
        cudaStreamCreateWithFlags(&hs_s3, cudaStreamNonBlocking);
        cudaEventCreateWithFlags(&hs_ev0, cudaEventDisableTiming);
        cudaEventCreateWithFlags(&hs_ev2, cudaEventDisableTiming);
        cudaEventCreateWithFlags(&hs_ev3, cudaEventDisableTiming);
        cudaEventCreateWithFlags(&hs_ev5, cudaEventDisableTiming);
        cudaEventCreateWithFlags(&hs_evEnd, cudaEventDisableTiming);
    }
};
HsInitStreams hs_init_streams;
}

// ---------------- launch ----------------
extern "C" void kernel_launch(void* const* d_in, const int* in_sizes, int n_in,
                              void* d_out, int out_size) {
    const float* h     = (const float*)d_in[0];
    const float* W     = (const float*)d_in[1];
    const float* a     = (const float*)d_in[2];
    const float* disc  = (const float*)d_in[3];
    const int*   kmask = (const int*)d_in[4];
    const float* lamda = (const float*)d_in[5];

    float* outp = (float*)d_out;
    float* dnp  = outp + (size_t)NN * OUTD;
    float* kmp  = dnp + (size_t)NN * NN;

    const int GEMM_SMEM_WH  = 1024 + 3 * 49152;    // 148480
    const int GEMM_SMEM_ATT = 1024 + 2 * 65536;    // 132096
    cudaFuncSetAttribute(gemm_att, cudaFuncAttributeMaxDynamicSharedMemorySize, GEMM_SMEM_ATT);
    cudaFuncSetAttribute(gemm_wh,  cudaFuncAttributeMaxDynamicSharedMemorySize, GEMM_SMEM_WH);

    // origin stream: prep, then fork
    prep_all<<<PREP_HSPLIT + PREP_WD + PREP_WT + 1, 256>>>(h, W, disc);
    cudaEventRecord(hs_ev0, 0);

    // s2: u/v (needs prep's wd tables)
    cudaStreamWaitEvent(hs_s2, hs_ev0, 0);
    k_uv<<<NN / 8, 256, 0, hs_s2>>>(h);
    cudaEventRecord(hs_ev2, hs_s2);

    // s1: attention prologue (needs prep's h/W splits)
    cudaStreamWaitEvent(hs_s1, hs_ev0, 0);
    dim3 gg(OUTD / TN, NN / TM);                   // (4, 32)
    dim3 gh(OUTD / TN, NN / TM / 2);               // (4, 16) half-M grids
    gemm_wh<<<gg, 256, GEMM_SMEM_WH, hs_s1>>>();
    k_sbt<<<NN / 32, 256, 0, hs_s1>>>(a);

    // s1: fused half 0 (rows 0..2047), needs k_uv too
    cudaStreamWaitEvent(hs_s1, hs_ev2, 0);
    k_fused<<<NN / 2, 256, 0, hs_s1>>>(kmask, lamda, dnp, kmp, 0);
    cudaEventRecord(hs_ev3, hs_s1);

    // s3: gemm_att half 0 — overlaps with k_fused half 1 on s1
    cudaStreamWaitEvent(hs_s3, hs_ev3, 0);
    gemm_att<<<gh, 256, GEMM_SMEM_ATT, hs_s3>>>(outp, 0);
    cudaEventRecord(hs_ev5, hs_s3);

    // s1: fused half 1, then gemm_att half 1
    k_fused<<<NN / 2, 256, 0, hs_s1>>>(kmask, lamda, dnp, kmp, NN / 2);
    gemm_att<<<gh, 256, GEMM_SMEM_ATT, hs_s1>>>(outp, NN / TM / 2);
    cudaEventRecord(hs_evEnd, hs_s1);

    // join both tails back to origin stream
    cudaStreamWaitEvent(0, hs_ev5, 0);
    cudaStreamWaitEvent(0, hs_evEnd, 0);
}

// round 17
// speedup vs baseline: 1.1884x; 1.1884x over previous
#include <cuda_runtime.h>
#include <cuda_bf16.h>
#include <math.h>
#include <stdint.h>

// Problem constants
#define NN   4096
#define IND  512
#define OUTD 256
#define KH   3
#define ALPHA 0.2f
#define BETA  0.1f
#define ETA   0.5f

// GEMM tiling
#define TM 128
#define TN 64
#define KC 64
#define KCA 128
#define NITER_ATT (NN / KCA)    // 32
#define NITER_WH  (IND / KC)    // 8

#if defined(__CUDA_ARCH__)
#  if (__CUDA_ARCH__ >= 1000) && (defined(__CUDA_ARCH_FEAT_SM103_ALL) || defined(__CUDA_ARCH_SPECIFIC__) || defined(__CUDA_ARCH_FAMILY_SPECIFIC__))
#    define USE_TC 1
#  else
#    define USE_TC 0
#  endif
#else
#  define USE_TC 0
#endif

// ---------------- device scratch ----------------
__device__ __nv_bfloat16 g_att_hi[(size_t)NN * NN];
__device__ float g_Wh0[(size_t)NN * OUTD];
__device__ __nv_bfloat16 g_BT_hi[(size_t)OUTD * NN];
__device__ __nv_bfloat16 g_BT_lo[(size_t)OUTD * NN];
__device__ __nv_bfloat16 g_h_hi[(size_t)NN * IND];
__device__ __nv_bfloat16 g_h_lo[(size_t)NN * IND];
__device__ __nv_bfloat16 g_WT_hi[(size_t)OUTD * IND];
__device__ __nv_bfloat16 g_WT_lo[(size_t)OUTD * IND];
__device__ float g_u[NN], g_v[NN];
__device__ float g_E1[NN], g_F1[NN];
__device__ float g_E2[NN], g_F2[NN];
__device__ float g_wd0[IND], g_wd1[IND];
__device__ unsigned g_ord[4];

// ---------------- ordered-float encoding ----------------
__device__ __forceinline__ unsigned ordenc(float f) {
    unsigned b = __float_as_uint(f);
    return (b & 0x80000000u) ? ~b : (b | 0x80000000u);
}
__device__ __forceinline__ float orddec(unsigned k) {
    unsigned b = (k & 0x80000000u) ? (k & 0x7FFFFFFFu) : ~k;
    return __uint_as_float(b);
}

// ---------------- PTX helpers ----------------
__device__ __forceinline__ uint32_t smem_u32(const void* p) {
    uint32_t a;
    asm("{ .reg .u64 t; cvta.to.shared.u64 t, %1; cvt.u32.u64 %0, t; }" : "=r"(a) : "l"(p));
    return a;
}
__device__ __forceinline__ uint32_t elect_one() {
    uint32_t p;
    asm volatile("{ .reg .pred p; elect.sync _|p, 0xFFFFFFFF; selp.b32 %0, 1, 0, p; }" : "=r"(p));
    return p;
}
#define MBARRIER_INIT(addr, cnt) \
    asm volatile("mbarrier.init.shared.b64 [%0], %1;" :: "r"(addr), "r"(cnt) : "memory")
#define MBARRIER_INVAL(addr) \
    asm volatile("mbarrier.inval.shared.b64 [%0];" :: "r"(addr) : "memory")
#define MBAR_WAIT(addr, ph) do { \
    uint32_t _m = (addr); uint32_t _p = (ph); uint32_t _d; \
    asm volatile("{ .reg .pred p; mbarrier.try_wait.parity.acquire.cta.shared::cta.b64 p, [%1], %2; selp.b32 %0, 1, 0, p; }" \
        : "=r"(_d) : "r"(_m), "r"(_p) : "memory"); \
    if (!_d) { \
        asm volatile("{ .reg .pred P1; WL_%=: mbarrier.try_wait.parity.acquire.cta.shared::cta.b64 P1, [%0], %1, 0x989680; @P1 bra.uni WD_%=; bra.uni WL_%=; WD_%=: }" \
            :: "r"(_m), "r"(_p) : "memory"); \
    } } while (0)

#if USE_TC
#define TCGEN05_ALLOC(saddr, ncols) \
    asm volatile("tcgen05.alloc.cta_group::1.sync.aligned.shared::cta.b32 [%0], %1;" :: "r"(saddr), "r"(ncols) : "memory")
#define TCGEN05_DEALLOC(tmem, ncols) \
    asm volatile("tcgen05.dealloc.cta_group::1.sync.aligned.b32 %0, %1;" :: "r"(tmem), "r"(ncols))
#define TCGEN05_COMMIT(mbar) \
    asm volatile("tcgen05.commit.cta_group::1.mbarrier::arrive::one.shared::cluster.b64 [%0];" :: "r"(mbar) : "memory")
#define TCGEN05_WAIT_LD() asm volatile("tcgen05.wait::ld.sync.aligned;" ::: "memory")
#define TCGEN05_FENCE_AFTER() asm volatile("tcgen05.fence::after_thread_sync;" ::: "memory")
#define TCGEN05_FENCE_BEFORE() asm volatile("tcgen05.fence::before_thread_sync;" ::: "memory")
#define TCGEN05_LD_X32(r, addr) \
    asm volatile("tcgen05.ld.sync.aligned.32x32b.x32.b32 " \
        "{%0,%1,%2,%3,%4,%5,%6,%7,%8,%9,%10,%11,%12,%13,%14,%15," \
        "%16,%17,%18,%19,%20,%21,%22,%23,%24,%25,%26,%27,%28,%29,%30,%31}, [%32];" \
        : "=r"((r)[0]),"=r"((r)[1]),"=r"((r)[2]),"=r"((r)[3]),"=r"((r)[4]),"=r"((r)[5]),"=r"((r)[6]),"=r"((r)[7]), \
          "=r"((r)[8]),"=r"((r)[9]),"=r"((r)[10]),"=r"((r)[11]),"=r"((r)[12]),"=r"((r)[13]),"=r"((r)[14]),"=r"((r)[15]), \
          "=r"((r)[16]),"=r"((r)[17]),"=r"((r)[18]),"=r"((r)[19]),"=r"((r)[20]),"=r"((r)[21]),"=r"((r)[22]),"=r"((r)[23]), \
          "=r"((r)[24]),"=r"((r)[25]),"=r"((r)[26]),"=r"((r)[27]),"=r"((r)[28]),"=r"((r)[29]),"=r"((r)[30]),"=r"((r)[31]) \
        : "r"(addr))

static __device__ __forceinline__ uint64_t make_desc(uint32_t addr) {
    const uint64_t base = (uint64_t(2) << 61) | (uint64_t(1) << 46) |
                          (uint64_t(64) << 32) | (uint64_t(1) << 16);
    return base | ((uint64_t)(addr >> 4) & 0x3FFF);
}

#define IDESC ((1u << 4) | (1u << 7) | (1u << 10) | ((TN / 8) << 17) | ((TM / 16) << 24))

__device__ __forceinline__ void mma_ss_f16(uint32_t d, uint64_t a, uint64_t b,
                                           uint32_t idesc, uint32_t acc) {
    asm volatile(
        "{\n\t.reg .pred p;\n\t"
        "setp.ne.u32 p, %4, 0;\n\t"
        "tcgen05.mma.cta_group::1.kind::f16 [%0], %1, %2, %3, {%5,%5,%5,%5}, p;\n\t}"
        :: "r"(d), "l"(a), "l"(b), "r"(idesc), "r"(acc), "r"(0u) : "memory");
}
#endif  // USE_TC

__device__ __forceinline__ void cpa16(uint32_t s, const void* g) {
    asm volatile("cp.async.cg.shared.global [%0], [%1], 16;" :: "r"(s), "l"(g));
}

// ---------------- K0: fused prep ----------------
#define PREP_HSPLIT 2048
#define PREP_WD     512
#define PREP_WT     128
__global__ void __launch_bounds__(256)
prep_all(const float* __restrict__ h, const float* __restrict__ W,
         const float* __restrict__ disc) {
    __shared__ float shbuf[32 * 33];
    int b = blockIdx.x;
    int t = threadIdx.x;

    if (b < PREP_HSPLIT) {
        int idx = b * 256 + t;
        const float4* h4 = (const float4*)h;
        float4 v = h4[idx];
        __nv_bfloat16 hx = __float2bfloat16(v.x), hy = __float2bfloat16(v.y);
        __nv_bfloat16 hz = __float2bfloat16(v.z), hw = __float2bfloat16(v.w);
        __nv_bfloat162* hi2 = (__nv_bfloat162*)g_h_hi;
        __nv_bfloat162* lo2 = (__nv_bfloat162*)g_h_lo;
        hi2[2 * idx]     = __nv_bfloat162(hx, hy);
        hi2[2 * idx + 1] = __nv_bfloat162(hz, hw);
        lo2[2 * idx]     = __nv_bfloat162(__float2bfloat16(v.x - __bfloat162float(hx)),
                                          __float2bfloat16(v.y - __bfloat162float(hy)));
        lo2[2 * idx + 1] = __nv_bfloat162(__float2bfloat16(v.z - __bfloat162float(hz)),
                                          __float2bfloat16(v.w - __bfloat162float(hw)));
    } else if (b < PREP_HSPLIT + PREP_WD) {
        int i = b - PREP_HSPLIT;
        float d0 = disc[t];
        float d1 = disc[OUTD + t];
        float p0 = 0.f, p1 = 0.f, w = 1.f;
#pragma unroll
        for (int k = 0; k < KH; k++) {
            float wv = W[((size_t)(k * IND + i)) * OUTD + t];
            p0 += w * wv * d0;
            p1 += w * wv * d1;
            w *= ETA;
        }
        float* sh0 = shbuf;
        float* sh1 = shbuf + 256;
        sh0[t] = p0; sh1[t] = p1;
        __syncthreads();
        for (int o = 128; o; o >>= 1) {
            if (t < o) { sh0[t] += sh0[t + o]; sh1[t] += sh1[t + o]; }
            __syncthreads();
        }
        if (t == 0) { g_wd0[i] = sh0[0]; g_wd1[i] = sh1[0]; }
    } else if (b < PREP_HSPLIT + PREP_WD + PREP_WT) {
        int tb = b - (PREP_HSPLIT + PREP_WD);
        int r0 = (tb & 15) * 32;
        int c0 = (tb >> 4) * 32;
        float (*sh)[33] = (float(*)[33])shbuf;
        int tx = t & 31, ty = t >> 5;
#pragma unroll
        for (int it = 0; it < 4; it++) {
            int r = ty + 8 * it;
            sh[r][tx] = W[(size_t)(r0 + r) * OUTD + c0 + tx];
        }
        __syncthreads();
#pragma unroll
        for (int it = 0; it < 4; it++) {
            int n = c0 + ty + 8 * it;
            int k = r0 + tx;
            float v = sh[tx][ty + 8 * it];
            __nv_bfloat16 hi = __float2bfloat16(v);
            g_WT_hi[(size_t)n * IND + k] = hi;
            g_WT_lo[(size_t)n * IND + k] = __float2bfloat16(v - __bfloat162float(hi));
        }
    } else {
        if (t == 0) {
            g_ord[0] = 0xFFFFFFFFu;
            g_ord[1] = 0u;
            g_ord[2] = 0xFFFFFFFFu;
            g_ord[3] = 0u;
        }
    }
}

// ---------------- K2: u/v + atomic min/max ----------------
__global__ void __launch_bounds__(256) k_uv(const float* __restrict__ h) {
    __shared__ float su[8], sv[8];
    int gw = (blockIdx.x * blockDim.x + threadIdx.x) >> 5;
    int lane = threadIdx.x & 31;
    int wid = threadIdx.x >> 5;
    const float* hr = h + (size_t)gw * IND;
    float u = 0.f, v = 0.f;
#pragma unroll 4
    for (int i = lane; i < IND; i += 32) {
        float hv = hr[i];
        u += hv * g_wd0[i];
        v += hv * g_wd1[i];
    }
#pragma unroll
    for (int o = 16; o; o >>= 1) {
        u += __shfl_down_sync(0xffffffffu, u, o);
        v += __shfl_down_sync(0xffffffffu, v, o);
    }
    if (lane == 0) {
        g_u[gw] = u; g_v[gw] = v;
        su[wid] = u; sv[wid] = v;
    }
    __syncthreads();
    if (threadIdx.x == 0) {
        float umin = su[0], umax = su[0], vmin = sv[0], vmax = sv[0];
#pragma unroll
        for (int i = 1; i < 8; i++) {
            umin = fminf(umin, su[i]); umax = fmaxf(umax, su[i]);
            vmin = fminf(vmin, sv[i]); vmax = fmaxf(vmax, sv[i]);
        }
        atomicMin(&g_ord[0], ordenc(umin));
        atomicMax(&g_ord[1], ordenc(umax));
        atomicMin(&g_ord[2], ordenc(vmin));
        atomicMax(&g_ord[3], ordenc(vmax));
    }
}

// ---------------- K5+K6 fused: s1/s2 (-> E/F tables) + Wh0^T hi/lo ----------
__global__ void __launch_bounds__(256)
k_sbt(const float* __restrict__ a) {
    __shared__ float sh[32][257];
    __shared__ float s_a1[OUTD], s_a2[OUTD];
    int tx = threadIdx.x & 31;
    int ty = threadIdx.x >> 5;
    int tid = threadIdx.x;
    int m0 = blockIdx.x * 32;

    s_a1[tid] = a[tid];
    s_a2[tid] = a[OUTD + tid];
#pragma unroll
    for (int i = 0; i < 4; i++) {
        int m = ty + 8 * i;
#pragma unroll
        for (int j = 0; j < 8; j++) {
            int n = tx + 32 * j;
            sh[m][n] = g_Wh0[(size_t)(m0 + m) * OUTD + n];
        }
    }
    __syncthreads();

#pragma unroll
    for (int i = 0; i < 4; i++) {
        int m = ty + 8 * i;
        float x1 = 0.f, x2 = 0.f;
#pragma unroll
        for (int j = 0; j < 8; j++) {
            int n = tx + 32 * j;
            float w = sh[m][n];
            x1 += w * s_a1[n];
            x2 += w * s_a2[n];
        }
#pragma unroll
        for (int o = 16; o; o >>= 1) {
            x1 += __shfl_down_sync(0xffffffffu, x1, o);
            x2 += __shfl_down_sync(0xffffffffu, x2, o);
        }
        if (tx == 0) {
            int m_g = m0 + m;
            g_E1[m_g] = __expf(x1);
            g_F1[m_g] = __expf(ALPHA * x1);
            g_E2[m_g] = __expf(x2);
            g_F2[m_g] = __expf(ALPHA * x2);
        }
    }

#pragma unroll
    for (int j = 0; j < 32; j++) {
        int n = ty + 8 * j;
        float v = sh[tx][n];
        __nv_bfloat16 hi = __float2bfloat16(v);
        g_BT_hi[(size_t)n * NN + m0 + tx] = hi;
        g_BT_lo[(size_t)n * NN + m0 + tx] = __float2bfloat16(v - __bfloat162float(hi));
    }
}

// ---------------- K7: FUSED att + dn + km (single mask pass) ----------------
// 32 KB smem (E2/F2 only); v read directly as coalesced float4 (L2-resident).
__global__ void __launch_bounds__(256)
k_fused(const int* __restrict__ kmask, const float* __restrict__ lamda,
        float* __restrict__ dn, float* __restrict__ km) {
    __shared__ float e2s[NN];   // 16 KB
    __shared__ float f2s[NN];   // 16 KB
    __shared__ float red[256];
    __shared__ float s_inv;
    int i = blockIdx.x;
    int t = threadIdx.x;  // 256
    for (int q = t; q < NN; q += 256) {
        e2s[q] = g_E2[q];
        f2s[q] = g_F2[q];
    }
    if (t == 0) {
        float umin = orddec(g_ord[0]), umax = orddec(g_ord[1]);
        float vmin = orddec(g_ord[2]), vmax = orddec(g_ord[3]);
        s_inv = 1.f / fmaxf(fabsf(umin + vmin), umax + vmax);
    }
    __syncthreads();

    float E1 = g_E1[i];
    float F1 = g_F1[i];
    float ui = g_u[i];
    float lam = lamda[0];
    float inv = s_inv;
    size_t rb = (size_t)i * NN;
    size_t plane = (size_t)NN * NN;
    const int4* m0p = (const int4*)(kmask + rb);
    const int4* m1p = (const int4*)(kmask + plane + rb);
    const int4* m2p = (const int4*)(kmask + 2 * plane + rb);
    const float4* v4p = (const float4*)g_v;

    float p[16];
    uint32_t b0 = 0, b1 = 0, b2 = 0;
    float sum = 0.f;
#pragma unroll
    for (int q = 0; q < 4; q++) {
        int j4 = t + 256 * q;
        int4 ma = __ldcs(&m0p[j4]);
        int4 mb = __ldcs(&m1p[j4]);
        int4 mc = __ldcs(&m2p[j4]);
        int base = 4 * j4;
#pragma unroll
        for (int c = 0; c < 4; c++) {
            int e = 4 * q + c;
            int a0 = (c == 0) ? ma.x : (c == 1) ? ma.y : (c == 2) ? ma.z : ma.w;
            int a1 = (c == 0) ? mb.x : (c == 1) ? mb.y : (c == 2) ? mb.z : mb.w;
            int a2 = (c == 0) ? mc.x : (c == 1) ? mc.y : (c == 2) ? mc.z : mc.w;
            b0 |= (uint32_t)a0 << e;
            b1 |= (uint32_t)a1 << e;
            b2 |= (uint32_t)a2 << e;
            float pv = E1 * e2s[base + c];
            if (pv <= 1.f) pv = F1 * f2s[base + c];
            pv = a0 ? pv : 0.f;
            p[e] = pv;
            sum += pv;
        }
    }
    red[t] = sum; __syncthreads();
    for (int o = 128; o; o >>= 1) { if (t < o) red[t] += red[t + o]; __syncthreads(); }
    float ri = 1.f / red[0];

    uint2* ah = (uint2*)(g_att_hi + rb);
    float4* dn4 = (float4*)(dn + rb);
    float4* k04 = (float4*)(km + rb);
    float4* k14 = (float4*)(km + plane + rb);
    float4* k24 = (float4*)(km + 2 * plane + rb);

#pragma unroll
    for (int q = 0; q < 4; q++) {
        int j4 = t + 256 * q;
        __nv_bfloat162 lo2(__float2bfloat16(p[4 * q + 0] * ri),
                           __float2bfloat16(p[4 * q + 1] * ri));
        __nv_bfloat162 hi2(__float2bfloat16(p[4 * q + 2] * ri),
                           __float2bfloat16(p[4 * q + 3] * ri));
        uint2 att_out;
        att_out.x = *(uint32_t*)&lo2;
        att_out.y = *(uint32_t*)&hi2;
        ah[j4] = att_out;

        float4 vv = __ldg(&v4p[j4]);
        float4 dno, k0, k1, k2;
#pragma unroll
        for (int c = 0; c < 4; c++) {
            int e = 4 * q + c;
            int a0 = (b0 >> e) & 1;
            int a1 = (b1 >> e) & 1;
            int a2 = (b2 >> e) & 1;
            float vj = (c == 0) ? vv.x : (c == 1) ? vv.y : (c == 2) ? vv.z : vv.w;
            float d = (ui + vj) * inv;
            int pos = d > lam;
            int neg = d < -lam;
            float dv = (pos | neg) ? 0.f : d;
            int km0 = a0 - a0 * pos - a1 * neg;
            int km1 = a1 + a0 * pos - a1 * pos + a1 * neg - a2 * neg;
            int km2 = a2 + a1 * pos + a2 * neg;
            float f0 = (float)km0, f1 = (float)km1, f2 = (float)km2;
            if (c == 0) { dno.x = dv; k0.x = f0; k1.x = f1; k2.x = f2; }
            else if (c == 1) { dno.y = dv; k0.y = f0; k1.y = f1; k2.y = f2; }
            else if (c == 2) { dno.z = dv; k0.z = f0; k1.z = f1; k2.z = f2; }
            else { dno.w = dv; k0.w = f0; k1.w = f1; k2.w = f2; }
        }
        __stcs(&dn4[j4], dno);
        __stcs(&k04[j4], k0);
        __stcs(&k14[j4], k1);
        __stcs(&k24[j4], k2);
    }
}

// ---------------- K8a: tcgen05 GEMM (TM128/TN64, KC=128, 2-stage) ------------
__global__ void __launch_bounds__(256)
gemm_att(float* __restrict__ outp) {
#if USE_TC
    extern __shared__ char smem[];
    const uint32_t sb = smem_u32(smem);
    int tid = threadIdx.x, wid = tid >> 5, lane = tid & 31;
    int m0 = blockIdx.y * TM;
    int n0 = blockIdx.x * TN;

    if (wid == 0) TCGEN05_ALLOC(sb + 0, 256);
    if (tid == 0) {
        MBARRIER_INIT(sb + 8, 1);
        MBARRIER_INIT(sb + 16, 1);
        MBARRIER_INIT(sb + 24, 1);
    }
    __syncthreads();
    uint32_t tmem;
    asm volatile("ld.shared.b32 %0, [%1];" : "=r"(tmem) : "r"(sb + 0));

    const char* gAh = (const char*)g_att_hi + (size_t)m0 * (NN * 2);
    const char* gBh = (const char*)g_BT_hi + (size_t)n0 * (NN * 2);
    const char* gBl = (const char*)g_BT_lo + (size_t)n0 * (NN * 2);

#define LOAD_STAGE_A(s, kc) do { \
    uint32_t sbase = sb + 1024 + (s) * 65536; \
    _Pragma("unroll") \
    for (int i_ = 0; i_ < 8; i_++) { \
        int q_ = tid + 256 * i_; \
        int sub_ = q_ >> 10, r_ = (q_ >> 3) & 127, c_ = q_ & 7; \
        uint32_t so_ = sub_ * 16384 + r_ * 128 + (((uint32_t)(c_ ^ (r_ & 7))) << 4); \
        size_t go_ = (size_t)r_ * (NN * 2) + (size_t)(kc) * (KCA * 2) + (sub_ * 8 + c_) * 16; \
        cpa16(sbase + so_, gAh + go_); \
    } \
    _Pragma("unroll") \
    for (int i_ = 0; i_ < 4; i_++) { \
        int q_ = tid + 256 * i_; \
        int sub_ = q_ >> 9, r_ = (q_ >> 3) & 63, c_ = q_ & 7; \
        uint32_t so_ = sub_ * 8192 + r_ * 128 + (((uint32_t)(c_ ^ (r_ & 7))) << 4); \
        size_t go_ = (size_t)r_ * (NN * 2) + (size_t)(kc) * (KCA * 2) + (sub_ * 8 + c_) * 16; \
        cpa16(sbase + 32768 + so_, gBh + go_); \
        cpa16(sbase + 49152 + so_, gBl + go_); \
    } \
    asm volatile("cp.async.commit_group;"); \
} while (0)

    int ph0 = 0, ph1 = 0;
    LOAD_STAGE_A(0, 0);

    for (int kc = 0; kc < NITER_ATT; kc++) {
        int s = kc & 1;
        if (kc + 1 < NITER_ATT) {
            int sn = s ^ 1;
            if (kc >= 1) {
                if (sn == 0) { MBAR_WAIT(sb + 8, ph0); ph0 ^= 1; }
                else         { MBAR_WAIT(sb + 16, ph1); ph1 ^= 1; }
            }
            LOAD_STAGE_A(sn, kc + 1);
            asm volatile("cp.async.wait_group 1;");
        } else {
            asm volatile("cp.async.wait_group 0;");
        }
        __syncthreads();
        if (wid == 0) {
            if (elect_one()) {
                asm volatile("fence.proxy.async.shared::cta;" ::: "memory");
                uint32_t sbase = sb + 1024 + s * 65536;
#pragma unroll
                for (int sub = 0; sub < 2; sub++) {
                    uint64_t da  = make_desc(sbase + sub * 16384);
                    uint64_t dbh = make_desc(sbase + 32768 + sub * 8192);
                    uint64_t dbl = make_desc(sbase + 49152 + sub * 8192);
#pragma unroll
                    for (int ks = 0; ks < 4; ks++) {
                        uint32_t acc = (kc > 0) || (sub > 0) || (ks > 0);
                        mma_ss_f16(tmem, da + ks * 2, dbh + ks * 2, IDESC, acc);
                        mma_ss_f16(tmem, da + ks * 2, dbl + ks * 2, IDESC, 1);
                    }
                }
                TCGEN05_COMMIT(sb + 8 + s * 8);
            }
        }
    }

    if (wid == 0) {
        if (elect_one()) TCGEN05_COMMIT(sb + 24);
    }
    MBAR_WAIT(sb + 24, 0);
    TCGEN05_FENCE_AFTER();

    if (wid < 4) {
        int m = m0 + wid * 32 + lane;
        const float* whrow = g_Wh0 + (size_t)m * OUTD + n0;
        float* orow = outp + (size_t)m * OUTD + n0;
#pragma unroll
        for (int nb = 0; nb < TN; nb += 32) {
            uint32_t r[32];
            TCGEN05_LD_X32(r, tmem + nb);
            TCGEN05_WAIT_LD();
#pragma unroll
            for (int c = 0; c < 32; c++) {
                float w = 0.9f * __uint_as_float(r[c]) + 0.1f * whrow[nb + c];
                orow[nb + c] = w > 0.f ? w : expm1f(w);
            }
        }
        TCGEN05_FENCE_BEFORE();
    }
    __syncthreads();
    if (tid == 0) { MBARRIER_INVAL(sb + 8); MBARRIER_INVAL(sb + 16); MBARRIER_INVAL(sb + 24); }
    __syncthreads();
    if (wid == 0) TCGEN05_DEALLOC(tmem, 256);
#undef LOAD_STAGE_A
#else
    int tid = threadIdx.x;
    int m0 = blockIdx.y * TM;
    int n0 = blockIdx.x * TN;
    int tr = (tid >> 3) * 4;
    int tc = (tid & 7) * 8;
    for (int r = 0; r < 4; r++) {
        int m = m0 + tr + r;
        for (int c = 0; c < 8; c++) {
            int n = n0 + tc + c;
            float acc = 0.f;
            for (int k = 0; k < NN; k++) {
                float av = __bfloat162float(g_att_hi[(size_t)m * NN + k]);
                float bv = __bfloat162float(g_BT_hi[(size_t)n * NN + k]) +
                           __bfloat162float(g_BT_lo[(size_t)n * NN + k]);
                acc += av * bv;
            }
            float w = 0.9f * acc + 0.1f * g_Wh0[(size_t)m * OUTD + n];
            outp[(size_t)m * OUTD + n] = w > 0.f ? w : expm1f(w);
        }
    }
#endif
}

// ---------------- K8b: tcgen05 GEMM (TM128/TN64, 3-stage): g_Wh0 = h @ W0 ----
__global__ void __launch_bounds__(256)
gemm_wh() {
#if USE_TC
    extern __shared__ char smem[];
    const uint32_t sb = smem_u32(smem);
    int tid = threadIdx.x, wid = tid >> 5, lane = tid & 31;
    int m0 = blockIdx.y * TM;
    int n0 = blockIdx.x * TN;

    if (wid == 0) TCGEN05_ALLOC(sb + 0, 256);
    if (tid == 0) {
        MBARRIER_INIT(sb + 8, 1);
        MBARRIER_INIT(sb + 16, 1);
        MBARRIER_INIT(sb + 24, 1);
        MBARRIER_INIT(sb + 32, 1);
    }
    __syncthreads();
    uint32_t tmem;
    asm volatile("ld.shared.b32 %0, [%1];" : "=r"(tmem) : "r"(sb + 0));

    const char* gAh = (const char*)g_h_hi  + (size_t)m0 * (IND * 2);
    const char* gAl = (const char*)g_h_lo  + (size_t)m0 * (IND * 2);
    const char* gBh = (const char*)g_WT_hi + (size_t)n0 * (IND * 2);
    const char* gBl = (const char*)g_WT_lo + (size_t)n0 * (IND * 2);

#define LOAD_STAGE_W(s, kc) do { \
    uint32_t sbase = sb + 1024 + (s) * 49152; \
    _Pragma("unroll") \
    for (int i_ = 0; i_ < 4; i_++) { \
        int q_ = tid + 256 * i_; \
        int r_ = q_ >> 3, c_ = q_ & 7; \
        uint32_t so_ = r_ * 128 + (((uint32_t)(c_ ^ (r_ & 7))) << 4); \
        size_t go_ = (size_t)r_ * (IND * 2) + (size_t)(kc) * (KC * 2) + c_ * 16; \
        cpa16(sbase + so_,         gAh + go_); \
        cpa16(sbase + 16384 + so_, gAl + go_); \
    } \
    _Pragma("unroll") \
    for (int i_ = 0; i_ < 2; i_++) { \
        int q_ = tid + 256 * i_; \
        int r_ = q_ >> 3, c_ = q_ & 7; \
        uint32_t so_ = r_ * 128 + (((uint32_t)(c_ ^ (r_ & 7))) << 4); \
        size_t go_ = (size_t)r_ * (IND * 2) + (size_t)(kc) * (KC * 2) + c_ * 16; \
        cpa16(sbase + 32768 + so_, gBh + go_); \
        cpa16(sbase + 40960 + so_, gBl + go_); \
    } \
    asm volatile("cp.async.commit_group;"); \
} while (0)

    int ph[3] = {0, 0, 0};
    LOAD_STAGE_W(0, 0);
    LOAD_STAGE_W(1, 1);

    for (int kc = 0; kc < NITER_WH; kc++) {
        int s = kc % 3;
        if (kc + 2 < NITER_WH) {
            if (kc >= 1) {
                int rs = (kc - 1) % 3;
                MBAR_WAIT(sb + 8 + rs * 8, ph[rs]);
                ph[rs] ^= 1;
            }
            LOAD_STAGE_W((kc + 2) % 3, kc + 2);
            asm volatile("cp.async.wait_group 2;");
        } else if (kc + 1 < NITER_WH) {
            asm volatile("cp.async.wait_group 1;");
        } else {
            asm volatile("cp.async.wait_group 0;");
        }
        __syncthreads();
        if (wid == 0) {
            if (elect_one()) {
                asm volatile("fence.proxy.async.shared::cta;" ::: "memory");
                uint32_t sbase = sb + 1024 + s * 49152;
                uint64_t dah = make_desc(sbase);
                uint64_t dal = make_desc(sbase + 16384);
                uint64_t dbh = make_desc(sbase + 32768);
                uint64_t dbl = make_desc(sbase + 40960);
#pragma unroll
                for (int ks = 0; ks < 4; ks++) {
                    uint32_t acc = (kc > 0) || (ks > 0);
                    mma_ss_f16(tmem, dah + ks * 2, dbh + ks * 2, IDESC, acc);
                    mma_ss_f16(tmem, dal + ks * 2, dbh + ks * 2, IDESC, 1);
                    mma_ss_f16(tmem, dah + ks * 2, dbl + ks * 2, IDESC, 1);
                }
                TCGEN05_COMMIT(sb + 8 + s * 8);
            }
        }
    }

    if (wid == 0) {
        if (elect_one()) TCGEN05_COMMIT(sb + 32);
    }
    MBAR_WAIT(sb + 32, 0);
    TCGEN05_FENCE_AFTER();

    if (wid < 4) {
        int m = m0 + wid * 32 + lane;
        float* crow = g_Wh0 + (size_t)m * OUTD + n0;
#pragma unroll
        for (int nb = 0; nb < TN; nb += 32) {
            uint32_t r[32];
            TCGEN05_LD_X32(r, tmem + nb);
            TCGEN05_WAIT_LD();
#pragma unroll
            for (int c = 0; c < 32; c++) {
                crow[nb + c] = __uint_as_float(r[c]);
            }
        }
        TCGEN05_FENCE_BEFORE();
    }
    __syncthreads();
    if (tid == 0) {
        MBARRIER_INVAL(sb + 8); MBARRIER_INVAL(sb + 16);
        MBARRIER_INVAL(sb + 24); MBARRIER_INVAL(sb + 32);
    }
    __syncthreads();
    if (wid == 0) TCGEN05_DEALLOC(tmem, 256);
#undef LOAD_STAGE_W
#else
    int tid = threadIdx.x;
    int m0 = blockIdx.y * TM;
    int n0 = blockIdx.x * TN;
    int tr = (tid >> 3) * 4;
    int tc = (tid & 7) * 8;
    for (int r = 0; r < 4; r++) {
        int m = m0 + tr + r;
        for (int c = 0; c < 8; c++) {
            int n = n0 + tc + c;
            float acc = 0.f;
            for (int k = 0; k < IND; k++) {
                float av = __bfloat162float(g_h_hi[(size_t)m * IND + k]) +
                           __bfloat162float(g_h_lo[(size_t)m * IND + k]);
                float bv = __bfloat162float(g_WT_hi[(size_t)n * IND + k]) +
                           __bfloat162float(g_WT_lo[(size_t)n * IND + k]);
                acc += av * bv;
            }
            g_Wh0[(size_t)m * OUTD + n] = acc;
        }
    }
#endif
}

// ---------------- stream/event globals ----------------
static cudaStream_t hs_stream2 = nullptr;
static cudaEvent_t hs_ev1 = nullptr, hs_ev2 = nullptr;
namespace {
struct HsInitStreams {
    HsInitStreams() {
        cudaStreamCreateWithFlags(&hs_stream2, cudaStreamNonBlocking);
        cudaEventCreateWithFlags(&hs_ev1, cudaEventDisableTiming);
        cudaEventCreateWithFlags(&hs_ev2, cudaEventDisableTiming);
    }
};
HsInitStreams hs_init_streams;
}

// ---------------- launch ----------------
extern "C" void kernel_launch(void* const* d_in, const int* in_sizes, int n_in,
                              void* d_out, int out_size) {
    const float* h     = (const float*)d_in[0];
    const float* W     = (const float*)d_in[1];
    const float* a     = (const float*)d_in[2];
    const float* disc  = (const float*)d_in[3];
    const int*   kmask = (const int*)d_in[4];
    const float* lamda = (const float*)d_in[5];

    float* outp = (float*)d_out;                   // [NN, OUTD]
    float* dnp  = outp + (size_t)NN * OUTD;        // [NN, NN]
    float* kmp  = dnp + (size_t)NN * NN;           // [3, NN, NN]

    const int GEMM_SMEM_WH  = 1024 + 3 * 49152;    // 148480
    const int GEMM_SMEM_ATT = 1024 + 2 * 65536;    // 132096
    cudaFuncSetAttribute(gemm_att, cudaFuncAttributeMaxDynamicSharedMemorySize, GEMM_SMEM_ATT);
    cudaFuncSetAttribute(gemm_wh,  cudaFuncAttributeMaxDynamicSharedMemorySize, GEMM_SMEM_WH);

    // shared prep
    prep_all<<<PREP_HSPLIT + PREP_WD + PREP_WT + 1, 256>>>(h, W, disc);
    cudaEventRecord(hs_ev1, 0);
    cudaStreamWaitEvent(hs_stream2, hs_ev1, 0);

    // stream2: u/v + min/max (parallel with gemm_wh/k_sbt)
    k_uv<<<NN / 8, 256, 0, hs_stream2>>>(h);
    cudaEventRecord(hs_ev2, hs_stream2);

    // main stream: attention prologue
    dim3 gg(OUTD / TN, NN / TM);                   // (4, 32) = 128 CTAs
    gemm_wh<<<gg, 256, GEMM_SMEM_WH>>>();          // g_Wh0 = h @ W0
    k_sbt<<<NN / 32, 256>>>(a);                    // s1/s2 -> E/F tables + BT hi/lo

    // fused single-pass over masks: att + dn + km (needs k_uv results)
    cudaStreamWaitEvent(0, hs_ev2, 0);
    k_fused<<<NN, 256>>>(kmask, lamda, dnp, kmp);

    gemm_att<<<gg, 256, GEMM_SMEM_ATT>>>(outp);    // elu(0.9*att@Wh0 + 0.1*Wh0)
}